// round 4
// baseline (speedup 1.0000x reference)
#include <cuda_runtime.h>
#include <mma.h>
#include <math.h>

using namespace nvcuda;

// Problem constants
#define BB   2
#define SS   2048
#define HH   2048
#define NH   16
#define DD   128
#define MM   (BB*SS)       // 4096 rows

// Scratch (device globals — no allocation allowed)
__device__ float g_q[(size_t)MM*HH];
__device__ float g_k[(size_t)MM*HH];
__device__ float g_v[(size_t)MM*HH];
__device__ float g_ctx[(size_t)MM*HH];
__device__ float g_cos[SS*64];
__device__ float g_sin[SS*64];

__device__ __forceinline__ float tf32r(float v) { return wmma::__float_to_tf32(v); }

// ---------------------------------------------------------------------------
// RoPE tables (double-precision libm, rounded through reference fp32 path)
// ---------------------------------------------------------------------------
__global__ void rope_tables_kernel() {
    int t = blockIdx.x * blockDim.x + threadIdx.x;
    if (t >= SS * 64) return;
    int i = t & 63;
    int s = t >> 6;
    double invf_d = pow(10000.0, -((double)(2 * i) / 128.0));
    float invf = (float)invf_d;
    float ang = (float)s * invf;        // fp32 product, same as reference
    double a = (double)ang;
    g_cos[t] = (float)cos(a);
    g_sin[t] = (float)sin(a);
}

__global__ void rope_apply_kernel(float* __restrict__ buf) {
    int t = blockIdx.x * blockDim.x + threadIdx.x;
    const int total = MM * NH * 64;
    if (t >= total) return;
    int d   = t & 63;
    int h   = (t >> 6) & (NH - 1);
    int row = t >> 10;
    int s   = row & (SS - 1);
    float c  = g_cos[(s << 6) + d];
    float sn = g_sin[(s << 6) + d];
    size_t idx = (size_t)row * HH + (h << 7) + d;
    float x1 = buf[idx];
    float x2 = buf[idx + 64];
    buf[idx]      = x1 * c - x2 * sn;
    buf[idx + 64] = x2 * c + x1 * sn;
}

// ---------------------------------------------------------------------------
// NT GEMM, 3xTF32. C[M,N] = A[M,K] * B[N,K]^T (row-major).
// hi/lo split done ONCE at smem-fill; smem double-buffered with register
// prefetch of the next K-tile. Block 128x128, K-step 32, 8 warps.
// ---------------------------------------------------------------------------
#define GLD 40   // smem leading dim (floats)
// one stage = Ah, Al, Bh, Bl tiles of 128 x GLD floats
#define G_STAGE (4 * 128 * GLD)
#define G_SMEM  (2 * G_STAGE * 4)

__global__ __launch_bounds__(256) void gemm_nt_3xtf32(
    const float* __restrict__ A, const float* __restrict__ Bm,
    float* __restrict__ C, int Md, int Nd, int Kd)
{
    extern __shared__ __align__(16) float sm[];

    const int tid = threadIdx.x;
    const int w   = tid >> 5;
    const int wm  = w >> 2;   // 0..1  (64 rows each)
    const int wn  = w & 3;    // 0..3  (32 cols each)
    const int bm  = blockIdx.y * 128;
    const int bn  = blockIdx.x * 128;

    wmma::fragment<wmma::accumulator, 16, 16, 8, float> acc[4][2];
    #pragma unroll
    for (int i = 0; i < 4; i++)
        #pragma unroll
        for (int j = 0; j < 2; j++)
            wmma::fill_fragment(acc[i][j], 0.0f);

    // per-thread prefetch slots: 4 float4 for A, 4 for B (128 rows x 8 f4-cols)
    float4 pa[4], pb[4];

    #pragma unroll
    for (int i = 0; i < 4; i++) {
        int l  = tid + i * 256;
        int m  = l >> 3;
        int k4 = l & 7;
        pa[i] = *(const float4*)&A [(size_t)(bm + m) * Kd + k4 * 4];
        pb[i] = *(const float4*)&Bm[(size_t)(bn + m) * Kd + k4 * 4];
    }

    // convert + store a stage
    auto stage_store = [&](int buf) {
        float* Ah = sm + buf * G_STAGE;
        float* Al = Ah + 128 * GLD;
        float* Bh = Al + 128 * GLD;
        float* Bl = Bh + 128 * GLD;
        #pragma unroll
        for (int i = 0; i < 4; i++) {
            int l  = tid + i * 256;
            int m  = l >> 3;
            int k4 = l & 7;
            float4 va = pa[i], vb = pb[i];
            float4 h, lo;
            h.x = tf32r(va.x); lo.x = tf32r(va.x - h.x);
            h.y = tf32r(va.y); lo.y = tf32r(va.y - h.y);
            h.z = tf32r(va.z); lo.z = tf32r(va.z - h.z);
            h.w = tf32r(va.w); lo.w = tf32r(va.w - h.w);
            *(float4*)&Ah[m * GLD + k4 * 4] = h;
            *(float4*)&Al[m * GLD + k4 * 4] = lo;
            h.x = tf32r(vb.x); lo.x = tf32r(vb.x - h.x);
            h.y = tf32r(vb.y); lo.y = tf32r(vb.y - h.y);
            h.z = tf32r(vb.z); lo.z = tf32r(vb.z - h.z);
            h.w = tf32r(vb.w); lo.w = tf32r(vb.w - h.w);
            *(float4*)&Bh[m * GLD + k4 * 4] = h;
            *(float4*)&Bl[m * GLD + k4 * 4] = lo;
        }
    };

    stage_store(0);
    __syncthreads();

    const int nk = Kd >> 5;
    for (int kt = 0; kt < nk; kt++) {
        int cur = kt & 1;

        if (kt + 1 < nk) {
            int k0 = (kt + 1) << 5;
            #pragma unroll
            for (int i = 0; i < 4; i++) {
                int l  = tid + i * 256;
                int m  = l >> 3;
                int k4 = l & 7;
                pa[i] = *(const float4*)&A [(size_t)(bm + m) * Kd + k0 + k4 * 4];
                pb[i] = *(const float4*)&Bm[(size_t)(bn + m) * Kd + k0 + k4 * 4];
            }
        }

        const float* Ah = sm + cur * G_STAGE;
        const float* Al = Ah + 128 * GLD;
        const float* Bh = Al + 128 * GLD;
        const float* Bl = Bh + 128 * GLD;

        #pragma unroll
        for (int kk = 0; kk < 4; kk++) {
            wmma::fragment<wmma::matrix_a, 16, 16, 8, wmma::precision::tf32, wmma::row_major> a_hi[4], a_lo[4];
            wmma::fragment<wmma::matrix_b, 16, 16, 8, wmma::precision::tf32, wmma::col_major> b_hi[2], b_lo[2];
            #pragma unroll
            for (int i = 0; i < 4; i++) {
                wmma::load_matrix_sync(a_hi[i], Ah + (wm * 64 + i * 16) * GLD + kk * 8, GLD);
                wmma::load_matrix_sync(a_lo[i], Al + (wm * 64 + i * 16) * GLD + kk * 8, GLD);
            }
            #pragma unroll
            for (int j = 0; j < 2; j++) {
                wmma::load_matrix_sync(b_hi[j], Bh + (wn * 32 + j * 16) * GLD + kk * 8, GLD);
                wmma::load_matrix_sync(b_lo[j], Bl + (wn * 32 + j * 16) * GLD + kk * 8, GLD);
            }
            #pragma unroll
            for (int i = 0; i < 4; i++)
                #pragma unroll
                for (int j = 0; j < 2; j++) {
                    wmma::mma_sync(acc[i][j], a_hi[i], b_hi[j], acc[i][j]);
                    wmma::mma_sync(acc[i][j], a_lo[i], b_hi[j], acc[i][j]);
                    wmma::mma_sync(acc[i][j], a_hi[i], b_lo[j], acc[i][j]);
                }
        }

        if (kt + 1 < nk) stage_store(1 - cur);
        __syncthreads();
    }

    #pragma unroll
    for (int i = 0; i < 4; i++)
        #pragma unroll
        for (int j = 0; j < 2; j++)
            wmma::store_matrix_sync(
                C + (size_t)(bm + wm * 64 + i * 16) * Nd + bn + wn * 32 + j * 16,
                acc[i][j], Nd, wmma::mem_row_major);
}

// ---------------------------------------------------------------------------
// Flash attention (causal). hi/lo split for Q and K done once at tile load;
// V and P pre-rounded to tf32 (numerically identical to per-fragment cvt).
// ---------------------------------------------------------------------------
#define ATT_LD 136
#define PS_LD  72
// Qh, Ql, Kh, Kl, Vs (64 x ATT_LD each) + Ps (64 x PS_LD)
#define ATT_SMEM ((5 * 64 * ATT_LD + 64 * PS_LD) * 4)

__global__ __launch_bounds__(256) void attn_kernel() {
    const int qt = (int)gridDim.x - 1 - (int)blockIdx.x;  // heavy tiles first
    const int h  = blockIdx.y;
    const int b  = blockIdx.z;

    extern __shared__ __align__(16) float sm[];
    float* Qh = sm;
    float* Ql = Qh + 64 * ATT_LD;
    float* Kh = Ql + 64 * ATT_LD;   // doubles as the P*V result buffer
    float* Kl = Kh + 64 * ATT_LD;
    float* Vs = Kl + 64 * ATT_LD;
    float* Ps = Vs + 64 * ATT_LD;

    const int tid  = threadIdx.x;
    const int w    = tid >> 5;
    const int wm   = w >> 1;   // 0..3 (16 q-rows each)
    const int wn   = w & 1;    // 0..1

    const float* qp = g_q + (size_t)b * SS * HH + (size_t)h * DD;
    const float* kp = g_k + (size_t)b * SS * HH + (size_t)h * DD;
    const float* vp = g_v + (size_t)b * SS * HH + (size_t)h * DD;

    // Load + split Q tile (resident for whole block)
    for (int l = tid; l < 64 * 32; l += 256) {
        int rr = l >> 5, c4 = l & 31;
        float4 v = *(const float4*)&qp[(size_t)(qt * 64 + rr) * HH + c4 * 4];
        float4 hv, lv;
        hv.x = tf32r(v.x); lv.x = tf32r(v.x - hv.x);
        hv.y = tf32r(v.y); lv.y = tf32r(v.y - hv.y);
        hv.z = tf32r(v.z); lv.z = tf32r(v.z - hv.z);
        hv.w = tf32r(v.w); lv.w = tf32r(v.w - hv.w);
        *(float4*)&Qh[rr * ATT_LD + c4 * 4] = hv;
        *(float4*)&Ql[rr * ATT_LD + c4 * 4] = lv;
    }

    const int r    = tid >> 2;   // softmax/O row owned by this thread (4 thr/row)
    const int sub  = tid & 3;
    const int qglob = qt * 64 + r;
    const float SCALE = sqrtf(128.0f);

    float row_m = -INFINITY;
    float row_l = 0.0f;
    float o[32];
    #pragma unroll
    for (int i = 0; i < 32; i++) o[i] = 0.0f;

    for (int kt = 0; kt <= qt; ++kt) {
        const int kbase = kt * 64;
        __syncthreads();  // prior O-update reads of Kh done before overwrite

        for (int l = tid; l < 64 * 32; l += 256) {
            int rr = l >> 5, c4 = l & 31;
            size_t g = (size_t)(kbase + rr) * HH + c4 * 4;
            float4 kv = *(const float4*)&kp[g];
            float4 vv = *(const float4*)&vp[g];
            float4 hv, lv;
            hv.x = tf32r(kv.x); lv.x = tf32r(kv.x - hv.x);
            hv.y = tf32r(kv.y); lv.y = tf32r(kv.y - hv.y);
            hv.z = tf32r(kv.z); lv.z = tf32r(kv.z - hv.z);
            hv.w = tf32r(kv.w); lv.w = tf32r(kv.w - hv.w);
            *(float4*)&Kh[rr * ATT_LD + c4 * 4] = hv;
            *(float4*)&Kl[rr * ATT_LD + c4 * 4] = lv;
            vv.x = tf32r(vv.x); vv.y = tf32r(vv.y);
            vv.z = tf32r(vv.z); vv.w = tf32r(vv.w);
            *(float4*)&Vs[rr * ATT_LD + c4 * 4] = vv;
        }
        __syncthreads();

        // ---- scores = Q * K^T (3xTF32), warp tile 16x32, conversion-free ----
        {
            wmma::fragment<wmma::accumulator, 16, 16, 8, float> sacc[2];
            wmma::fill_fragment(sacc[0], 0.0f);
            wmma::fill_fragment(sacc[1], 0.0f);
            #pragma unroll
            for (int ks = 0; ks < 16; ks++) {
                wmma::fragment<wmma::matrix_a, 16, 16, 8, wmma::precision::tf32, wmma::row_major> a_hi, a_lo;
                wmma::load_matrix_sync(a_hi, Qh + (wm * 16) * ATT_LD + ks * 8, ATT_LD);
                wmma::load_matrix_sync(a_lo, Ql + (wm * 16) * ATT_LD + ks * 8, ATT_LD);
                #pragma unroll
                for (int j = 0; j < 2; j++) {
                    wmma::fragment<wmma::matrix_b, 16, 16, 8, wmma::precision::tf32, wmma::col_major> b_hi, b_lo;
                    wmma::load_matrix_sync(b_hi, Kh + (wn * 32 + j * 16) * ATT_LD + ks * 8, ATT_LD);
                    wmma::load_matrix_sync(b_lo, Kl + (wn * 32 + j * 16) * ATT_LD + ks * 8, ATT_LD);
                    wmma::mma_sync(sacc[j], a_hi, b_hi, sacc[j]);
                    wmma::mma_sync(sacc[j], a_lo, b_hi, sacc[j]);
                    wmma::mma_sync(sacc[j], a_hi, b_lo, sacc[j]);
                }
            }
            #pragma unroll
            for (int j = 0; j < 2; j++)
                wmma::store_matrix_sync(Ps + (wm * 16) * PS_LD + wn * 32 + j * 16,
                                        sacc[j], PS_LD, wmma::mem_row_major);
        }
        __syncthreads();

        // ---- online softmax (4 threads per row, 16 cols each) ----
        float alpha;
        {
            float vals[16];
            float tmax = -INFINITY;
            #pragma unroll
            for (int c0 = 0; c0 < 16; c0++) {
                int c = sub * 16 + c0;
                float sc = Ps[r * PS_LD + c] * SCALE;
                if (kbase + c > qglob) sc = -INFINITY;
                vals[c0] = sc;
                tmax = fmaxf(tmax, sc);
            }
            tmax = fmaxf(tmax, __shfl_xor_sync(0xffffffffu, tmax, 1));
            tmax = fmaxf(tmax, __shfl_xor_sync(0xffffffffu, tmax, 2));
            float newm = fmaxf(row_m, tmax);
            float lsum = 0.0f;
            #pragma unroll
            for (int c0 = 0; c0 < 16; c0++) {
                float p = __expf(vals[c0] - newm);
                Ps[r * PS_LD + sub * 16 + c0] = tf32r(p);  // pre-rounded for PV
                lsum += p;
            }
            lsum += __shfl_xor_sync(0xffffffffu, lsum, 1);
            lsum += __shfl_xor_sync(0xffffffffu, lsum, 2);
            alpha = __expf(row_m - newm);
            row_l = row_l * alpha + lsum;
            row_m = newm;
        }
        __syncthreads();

        // ---- O_tile = P * V (single-pass tf32), warp tile 16x64 ----
        {
            wmma::fragment<wmma::accumulator, 16, 16, 8, float> oac[4];
            #pragma unroll
            for (int j = 0; j < 4; j++) wmma::fill_fragment(oac[j], 0.0f);
            #pragma unroll
            for (int ks = 0; ks < 8; ks++) {
                wmma::fragment<wmma::matrix_a, 16, 16, 8, wmma::precision::tf32, wmma::row_major> pa;
                wmma::load_matrix_sync(pa, Ps + (wm * 16) * PS_LD + ks * 8, PS_LD);
                #pragma unroll
                for (int j = 0; j < 4; j++) {
                    wmma::fragment<wmma::matrix_b, 16, 16, 8, wmma::precision::tf32, wmma::row_major> vb;
                    wmma::load_matrix_sync(vb, Vs + (ks * 8) * ATT_LD + wn * 64 + j * 16, ATT_LD);
                    wmma::mma_sync(oac[j], pa, vb, oac[j]);
                }
            }
            #pragma unroll
            for (int j = 0; j < 4; j++)
                wmma::store_matrix_sync(Kh + (wm * 16) * ATT_LD + wn * 64 + j * 16,
                                        oac[j], ATT_LD, wmma::mem_row_major);
        }
        __syncthreads();

        // ---- O register update (interleaved cols: sub + 4*i) ----
        #pragma unroll
        for (int i = 0; i < 32; i++)
            o[i] = o[i] * alpha + Kh[r * ATT_LD + sub + 4 * i];
    }

    // ---- write ctx ----
    float inv = 1.0f / row_l;
    float* cp = g_ctx + (size_t)(b * SS + qglob) * HH + (size_t)h * DD;
    #pragma unroll
    for (int i = 0; i < 32; i++)
        cp[sub + 4 * i] = o[i] * inv;
}

// ---------------------------------------------------------------------------
// Launch
// ---------------------------------------------------------------------------
extern "C" void kernel_launch(void* const* d_in, const int* in_sizes, int n_in,
                              void* d_out, int out_size) {
    const float* x  = (const float*)d_in[0];
    const float* Wq = (const float*)d_in[1];
    const float* Wk = (const float*)d_in[2];
    const float* Wv = (const float*)d_in[3];
    const float* Wo = (const float*)d_in[4];
    float* out = (float*)d_out;

    float *q, *k, *v, *ctx;
    cudaGetSymbolAddress((void**)&q,   g_q);
    cudaGetSymbolAddress((void**)&k,   g_k);
    cudaGetSymbolAddress((void**)&v,   g_v);
    cudaGetSymbolAddress((void**)&ctx, g_ctx);

    cudaFuncSetAttribute(gemm_nt_3xtf32,
                         cudaFuncAttributeMaxDynamicSharedMemorySize, G_SMEM);
    cudaFuncSetAttribute(attn_kernel,
                         cudaFuncAttributeMaxDynamicSharedMemorySize, ATT_SMEM);

    rope_tables_kernel<<<(SS * 64 + 255) / 256, 256>>>();

    dim3 ggrid(HH / 128, MM / 128);  // (16, 32)
    gemm_nt_3xtf32<<<ggrid, 256, G_SMEM>>>(x, Wq, q, MM, HH, HH);
    gemm_nt_3xtf32<<<ggrid, 256, G_SMEM>>>(x, Wk, k, MM, HH, HH);
    gemm_nt_3xtf32<<<ggrid, 256, G_SMEM>>>(x, Wv, v, MM, HH, HH);

    int rt = MM * NH * 64;
    rope_apply_kernel<<<rt / 256, 256>>>(q);
    rope_apply_kernel<<<rt / 256, 256>>>(k);

    attn_kernel<<<dim3(SS / 64, NH, BB), 256, ATT_SMEM>>>();

    gemm_nt_3xtf32<<<ggrid, 256, G_SMEM>>>(ctx, Wo, out, MM, HH, HH);
}

// round 8
// speedup vs baseline: 2.2778x; 2.2778x over previous
#include <cuda_runtime.h>
#include <cuda_bf16.h>
#include <mma.h>
#include <math.h>
#include <cstdint>

using namespace nvcuda;

// Problem constants
#define BB   2
#define SS   2048
#define HH   2048
#define NH   16
#define DD   128
#define MM   (BB*SS)       // 4096 rows

// Scratch (device globals — no allocation allowed)
__device__ float g_q[(size_t)MM*HH];
__device__ float g_k[(size_t)MM*HH];
__device__ float g_v[(size_t)MM*HH];
__device__ float g_ctx[(size_t)MM*HH];
__device__ float g_cos[SS*64];
__device__ float g_sin[SS*64];

// ---------------------------------------------------------------------------
// bf16 hi/lo split helpers
// ---------------------------------------------------------------------------
__device__ __forceinline__ void bsplit(float v, __nv_bfloat16& h, __nv_bfloat16& l) {
    h = __float2bfloat16(v);
    l = __float2bfloat16(v - __bfloat162float(h));
}
__device__ __forceinline__ uint32_t bpack(__nv_bfloat16 a, __nv_bfloat16 b) {
    return (uint32_t)__bfloat16_as_ushort(a) | ((uint32_t)__bfloat16_as_ushort(b) << 16);
}
__device__ __forceinline__ void split4(float4 v, uint2& hi, uint2& lo) {
    __nv_bfloat16 hx, lx, hy, ly, hz, lz, hw, lw;
    bsplit(v.x, hx, lx); bsplit(v.y, hy, ly);
    bsplit(v.z, hz, lz); bsplit(v.w, hw, lw);
    hi.x = bpack(hx, hy); hi.y = bpack(hz, hw);
    lo.x = bpack(lx, ly); lo.y = bpack(lz, lw);
}

// ---------------------------------------------------------------------------
// RoPE tables (double-precision libm, rounded through reference fp32 path)
// ---------------------------------------------------------------------------
__global__ void rope_tables_kernel() {
    int t = blockIdx.x * blockDim.x + threadIdx.x;
    if (t >= SS * 64) return;
    int i = t & 63;
    int s = t >> 6;
    double invf_d = pow(10000.0, -((double)(2 * i) / 128.0));
    float invf = (float)invf_d;
    float ang = (float)s * invf;
    double a = (double)ang;
    g_cos[t] = (float)cos(a);
    g_sin[t] = (float)sin(a);
}

__global__ void rope_apply_kernel(float* __restrict__ buf) {
    int t = blockIdx.x * blockDim.x + threadIdx.x;
    const int total = MM * NH * 64;
    if (t >= total) return;
    int d   = t & 63;
    int h   = (t >> 6) & (NH - 1);
    int row = t >> 10;
    int s   = row & (SS - 1);
    float c  = g_cos[(s << 6) + d];
    float sn = g_sin[(s << 6) + d];
    size_t idx = (size_t)row * HH + (h << 7) + d;
    float x1 = buf[idx];
    float x2 = buf[idx + 64];
    buf[idx]      = x1 * c - x2 * sn;
    buf[idx + 64] = x2 * c + x1 * sn;
}

// ---------------------------------------------------------------------------
// NT GEMM, bf16x3 (hi/lo split). C[M,N] = A[M,K] * B[N,K]^T (row-major).
// Split done once at smem-fill (bf16 hi+lo = same bytes as f32, no extra LDS).
// Block 128x128, K-tile 32, double-buffered smem + register prefetch, 8 warps.
// ---------------------------------------------------------------------------
#define GLDB   40                      // smem leading dim (bf16 elements)
#define TILE_B (128 * GLDB * 2)        // 10240 B per tile
#define STG_B  (4 * TILE_B)            // Ah, Al, Bh, Bl
#define G_SMEM (2 * STG_B)             // 81920 B

#define GK 2048
#define GN 2048

__global__ __launch_bounds__(256) void gemm_nt_bf16x3(
    const float* __restrict__ A, const float* __restrict__ Bm,
    float* __restrict__ C)
{
    extern __shared__ __align__(16) char smem[];

    const int tid = threadIdx.x;
    const int w   = tid >> 5;
    const int wm  = w >> 2;   // 0..1  (64 rows each)
    const int wn  = w & 3;    // 0..3  (32 cols each)
    const int bm  = blockIdx.y * 128;
    const int bn  = blockIdx.x * 128;

    wmma::fragment<wmma::accumulator, 16, 16, 16, float> acc[4][2];
    #pragma unroll
    for (int i = 0; i < 4; i++)
        #pragma unroll
        for (int j = 0; j < 2; j++)
            wmma::fill_fragment(acc[i][j], 0.0f);

    // register prefetch slots: 128 rows x 8 float4-cols, 256 threads -> 4 each
    float4 pa[4], pb[4];

    auto load_regs = [&](int k0) {
        #pragma unroll
        for (int i = 0; i < 4; i++) {
            int l  = tid + i * 256;
            int m  = l >> 3;
            int k4 = l & 7;
            pa[i] = *(const float4*)&A [(size_t)(bm + m) * GK + k0 + k4 * 4];
            pb[i] = *(const float4*)&Bm[(size_t)(bn + m) * GK + k0 + k4 * 4];
        }
    };

    auto stage_store = [&](int buf) {
        char* base = smem + buf * STG_B;
        __nv_bfloat16* Ah = (__nv_bfloat16*)(base);
        __nv_bfloat16* Al = (__nv_bfloat16*)(base + TILE_B);
        __nv_bfloat16* Bh = (__nv_bfloat16*)(base + 2 * TILE_B);
        __nv_bfloat16* Bl = (__nv_bfloat16*)(base + 3 * TILE_B);
        #pragma unroll
        for (int i = 0; i < 4; i++) {
            int l  = tid + i * 256;
            int m  = l >> 3;
            int k4 = l & 7;
            uint2 h, lo;
            split4(pa[i], h, lo);
            *(uint2*)&Ah[m * GLDB + k4 * 4] = h;
            *(uint2*)&Al[m * GLDB + k4 * 4] = lo;
            split4(pb[i], h, lo);
            *(uint2*)&Bh[m * GLDB + k4 * 4] = h;
            *(uint2*)&Bl[m * GLDB + k4 * 4] = lo;
        }
    };

    load_regs(0);
    stage_store(0);
    __syncthreads();

    const int nk = GK / 32;   // 64 K-tiles
    for (int kt = 0; kt < nk; kt++) {
        const int cur = kt & 1;

        if (kt + 1 < nk) load_regs((kt + 1) * 32);   // LDG early, hide latency

        const char* base = smem + cur * STG_B;
        const __nv_bfloat16* Ah = (const __nv_bfloat16*)(base);
        const __nv_bfloat16* Al = (const __nv_bfloat16*)(base + TILE_B);
        const __nv_bfloat16* Bh = (const __nv_bfloat16*)(base + 2 * TILE_B);
        const __nv_bfloat16* Bl = (const __nv_bfloat16*)(base + 3 * TILE_B);

        #pragma unroll
        for (int kk = 0; kk < 2; kk++) {
            wmma::fragment<wmma::matrix_a, 16, 16, 16, __nv_bfloat16, wmma::row_major> a_hi[4], a_lo[4];
            wmma::fragment<wmma::matrix_b, 16, 16, 16, __nv_bfloat16, wmma::col_major> b_hi[2], b_lo[2];
            #pragma unroll
            for (int i = 0; i < 4; i++) {
                wmma::load_matrix_sync(a_hi[i], Ah + (wm * 64 + i * 16) * GLDB + kk * 16, GLDB);
                wmma::load_matrix_sync(a_lo[i], Al + (wm * 64 + i * 16) * GLDB + kk * 16, GLDB);
            }
            #pragma unroll
            for (int j = 0; j < 2; j++) {
                wmma::load_matrix_sync(b_hi[j], Bh + (wn * 32 + j * 16) * GLDB + kk * 16, GLDB);
                wmma::load_matrix_sync(b_lo[j], Bl + (wn * 32 + j * 16) * GLDB + kk * 16, GLDB);
            }
            #pragma unroll
            for (int i = 0; i < 4; i++)
                #pragma unroll
                for (int j = 0; j < 2; j++) {
                    wmma::mma_sync(acc[i][j], a_hi[i], b_hi[j], acc[i][j]);
                    wmma::mma_sync(acc[i][j], a_lo[i], b_hi[j], acc[i][j]);
                    wmma::mma_sync(acc[i][j], a_hi[i], b_lo[j], acc[i][j]);
                }
        }

        if (kt + 1 < nk) stage_store(1 - cur);
        __syncthreads();
    }

    #pragma unroll
    for (int i = 0; i < 4; i++)
        #pragma unroll
        for (int j = 0; j < 2; j++)
            wmma::store_matrix_sync(
                C + (size_t)(bm + wm * 64 + i * 16) * GN + bn + wn * 32 + j * 16,
                acc[i][j], GN, wmma::mem_row_major);
}

// ---------------------------------------------------------------------------
// Flash attention (causal), bf16x3 scores AND bf16x3 P*V (split P, split V).
// All splits happen once at smem fill / softmax write — inner loops are pure
// load_matrix_sync + mma_sync.
// ---------------------------------------------------------------------------
#define ALD    136   // bf16 leading dim for Q/K/V tiles (row = 272 B)
#define PS_LD  72    // f32 score tile leading dim
#define PLD    72    // bf16 P tile leading dim
#define OLD    136   // f32 O-scratch leading dim

// byte offsets in dynamic smem
#define OFF_QH  0
#define OFF_QL  (OFF_QH + 64 * ALD * 2)     // 17408
#define OFF_KH  (OFF_QL + 64 * ALD * 2)     // 34816
#define OFF_KL  (OFF_KH + 64 * ALD * 2)     // 52224
#define OFF_VH  (OFF_KL + 64 * ALD * 2)     // 69632
#define OFF_VL  (OFF_VH + 64 * ALD * 2)     // 87040
#define OFF_PS  (OFF_VL + 64 * ALD * 2)     // 104448
#define OFF_PH  (OFF_PS + 64 * PS_LD * 4)   // 122880
#define OFF_PL  (OFF_PH + 64 * PLD * 2)     // 132096
#define OFF_OS  (OFF_PL + 64 * PLD * 2)     // 141312
#define ATT_SMEM (OFF_OS + 64 * OLD * 4)    // 176128

__global__ __launch_bounds__(256) void attn_kernel() {
    const int qt = (int)gridDim.x - 1 - (int)blockIdx.x;  // heavy tiles first
    const int h  = blockIdx.y;
    const int b  = blockIdx.z;

    extern __shared__ __align__(16) char smc[];
    __nv_bfloat16* Qh = (__nv_bfloat16*)(smc + OFF_QH);
    __nv_bfloat16* Ql = (__nv_bfloat16*)(smc + OFF_QL);
    __nv_bfloat16* Kh = (__nv_bfloat16*)(smc + OFF_KH);
    __nv_bfloat16* Kl = (__nv_bfloat16*)(smc + OFF_KL);
    __nv_bfloat16* Vh = (__nv_bfloat16*)(smc + OFF_VH);
    __nv_bfloat16* Vl = (__nv_bfloat16*)(smc + OFF_VL);
    float*         Ps = (float*)        (smc + OFF_PS);
    __nv_bfloat16* Ph = (__nv_bfloat16*)(smc + OFF_PH);
    __nv_bfloat16* Pl = (__nv_bfloat16*)(smc + OFF_PL);
    float*         Os = (float*)        (smc + OFF_OS);

    const int tid = threadIdx.x;
    const int w   = tid >> 5;
    const int wm  = w >> 1;   // 0..3 (16 q-rows each)
    const int wn  = w & 1;    // 0..1

    const float* qp = g_q + (size_t)b * SS * HH + (size_t)h * DD;
    const float* kp = g_k + (size_t)b * SS * HH + (size_t)h * DD;
    const float* vp = g_v + (size_t)b * SS * HH + (size_t)h * DD;

    // Load + split Q tile (resident for whole block)
    for (int l = tid; l < 64 * 32; l += 256) {
        int rr = l >> 5, c4 = l & 31;
        float4 v = *(const float4*)&qp[(size_t)(qt * 64 + rr) * HH + c4 * 4];
        uint2 hv, lv;
        split4(v, hv, lv);
        *(uint2*)&Qh[rr * ALD + c4 * 4] = hv;
        *(uint2*)&Ql[rr * ALD + c4 * 4] = lv;
    }

    const int r     = tid >> 2;   // softmax/O row (4 threads per row)
    const int sub   = tid & 3;
    const int qglob = qt * 64 + r;
    const float SCALE = sqrtf(128.0f);

    float row_m = -INFINITY;
    float row_l = 0.0f;
    float o[32];
    #pragma unroll
    for (int i = 0; i < 32; i++) o[i] = 0.0f;

    for (int kt = 0; kt <= qt; ++kt) {
        const int kbase = kt * 64;
        __syncthreads();  // prior O-update reads of Os done; K/V overwrite safe

        for (int l = tid; l < 64 * 32; l += 256) {
            int rr = l >> 5, c4 = l & 31;
            size_t g = (size_t)(kbase + rr) * HH + c4 * 4;
            uint2 hv, lv;
            split4(*(const float4*)&kp[g], hv, lv);
            *(uint2*)&Kh[rr * ALD + c4 * 4] = hv;
            *(uint2*)&Kl[rr * ALD + c4 * 4] = lv;
            split4(*(const float4*)&vp[g], hv, lv);
            *(uint2*)&Vh[rr * ALD + c4 * 4] = hv;
            *(uint2*)&Vl[rr * ALD + c4 * 4] = lv;
        }
        __syncthreads();

        // ---- scores = Q * K^T (bf16x3), warp tile 16x32, conversion-free ----
        {
            wmma::fragment<wmma::accumulator, 16, 16, 16, float> sacc[2];
            wmma::fill_fragment(sacc[0], 0.0f);
            wmma::fill_fragment(sacc[1], 0.0f);
            #pragma unroll
            for (int ks = 0; ks < 8; ks++) {
                wmma::fragment<wmma::matrix_a, 16, 16, 16, __nv_bfloat16, wmma::row_major> a_hi, a_lo;
                wmma::load_matrix_sync(a_hi, Qh + (wm * 16) * ALD + ks * 16, ALD);
                wmma::load_matrix_sync(a_lo, Ql + (wm * 16) * ALD + ks * 16, ALD);
                #pragma unroll
                for (int j = 0; j < 2; j++) {
                    wmma::fragment<wmma::matrix_b, 16, 16, 16, __nv_bfloat16, wmma::col_major> b_hi, b_lo;
                    wmma::load_matrix_sync(b_hi, Kh + (wn * 32 + j * 16) * ALD + ks * 16, ALD);
                    wmma::load_matrix_sync(b_lo, Kl + (wn * 32 + j * 16) * ALD + ks * 16, ALD);
                    wmma::mma_sync(sacc[j], a_hi, b_hi, sacc[j]);
                    wmma::mma_sync(sacc[j], a_lo, b_hi, sacc[j]);
                    wmma::mma_sync(sacc[j], a_hi, b_lo, sacc[j]);
                }
            }
            #pragma unroll
            for (int j = 0; j < 2; j++)
                wmma::store_matrix_sync(Ps + (wm * 16) * PS_LD + wn * 32 + j * 16,
                                        sacc[j], PS_LD, wmma::mem_row_major);
        }
        __syncthreads();

        // ---- online softmax; write P as bf16 hi/lo ----
        float alpha;
        {
            float vals[16];
            float tmax = -INFINITY;
            #pragma unroll
            for (int c0 = 0; c0 < 16; c0++) {
                int c = sub * 16 + c0;
                float sc = Ps[r * PS_LD + c] * SCALE;
                if (kbase + c > qglob) sc = -INFINITY;
                vals[c0] = sc;
                tmax = fmaxf(tmax, sc);
            }
            tmax = fmaxf(tmax, __shfl_xor_sync(0xffffffffu, tmax, 1));
            tmax = fmaxf(tmax, __shfl_xor_sync(0xffffffffu, tmax, 2));
            float newm = fmaxf(row_m, tmax);
            float lsum = 0.0f;
            #pragma unroll
            for (int c0 = 0; c0 < 16; c0++) {
                float p = __expf(vals[c0] - newm);
                __nv_bfloat16 hp, lp;
                bsplit(p, hp, lp);
                Ph[r * PLD + sub * 16 + c0] = hp;
                Pl[r * PLD + sub * 16 + c0] = lp;
                lsum += p;
            }
            lsum += __shfl_xor_sync(0xffffffffu, lsum, 1);
            lsum += __shfl_xor_sync(0xffffffffu, lsum, 2);
            alpha = __expf(row_m - newm);
            row_l = row_l * alpha + lsum;
            row_m = newm;
        }
        __syncthreads();

        // ---- O_tile = P * V (bf16x3), warp tile 16x64 ----
        {
            wmma::fragment<wmma::accumulator, 16, 16, 16, float> oac[4];
            #pragma unroll
            for (int j = 0; j < 4; j++) wmma::fill_fragment(oac[j], 0.0f);
            #pragma unroll
            for (int ks = 0; ks < 4; ks++) {
                wmma::fragment<wmma::matrix_a, 16, 16, 16, __nv_bfloat16, wmma::row_major> p_hi, p_lo;
                wmma::load_matrix_sync(p_hi, Ph + (wm * 16) * PLD + ks * 16, PLD);
                wmma::load_matrix_sync(p_lo, Pl + (wm * 16) * PLD + ks * 16, PLD);
                #pragma unroll
                for (int j = 0; j < 4; j++) {
                    wmma::fragment<wmma::matrix_b, 16, 16, 16, __nv_bfloat16, wmma::row_major> v_hi, v_lo;
                    wmma::load_matrix_sync(v_hi, Vh + (ks * 16) * ALD + wn * 64 + j * 16, ALD);
                    wmma::load_matrix_sync(v_lo, Vl + (ks * 16) * ALD + wn * 64 + j * 16, ALD);
                    wmma::mma_sync(oac[j], p_hi, v_hi, oac[j]);
                    wmma::mma_sync(oac[j], p_lo, v_hi, oac[j]);
                    wmma::mma_sync(oac[j], p_hi, v_lo, oac[j]);
                }
            }
            #pragma unroll
            for (int j = 0; j < 4; j++)
                wmma::store_matrix_sync(Os + (wm * 16) * OLD + wn * 64 + j * 16,
                                        oac[j], OLD, wmma::mem_row_major);
        }
        __syncthreads();

        // ---- O register update (interleaved cols: sub + 4*i) ----
        #pragma unroll
        for (int i = 0; i < 32; i++)
            o[i] = o[i] * alpha + Os[r * OLD + sub + 4 * i];
    }

    // ---- write ctx ----
    float inv = 1.0f / row_l;
    float* cp = g_ctx + (size_t)(b * SS + qglob) * HH + (size_t)h * DD;
    #pragma unroll
    for (int i = 0; i < 32; i++)
        cp[sub + 4 * i] = o[i] * inv;
}

// ---------------------------------------------------------------------------
// Launch
// ---------------------------------------------------------------------------
extern "C" void kernel_launch(void* const* d_in, const int* in_sizes, int n_in,
                              void* d_out, int out_size) {
    const float* x  = (const float*)d_in[0];
    const float* Wq = (const float*)d_in[1];
    const float* Wk = (const float*)d_in[2];
    const float* Wv = (const float*)d_in[3];
    const float* Wo = (const float*)d_in[4];
    float* out = (float*)d_out;

    float *q, *k, *v, *ctx;
    cudaGetSymbolAddress((void**)&q,   g_q);
    cudaGetSymbolAddress((void**)&k,   g_k);
    cudaGetSymbolAddress((void**)&v,   g_v);
    cudaGetSymbolAddress((void**)&ctx, g_ctx);

    cudaFuncSetAttribute(gemm_nt_bf16x3,
                         cudaFuncAttributeMaxDynamicSharedMemorySize, G_SMEM);
    cudaFuncSetAttribute(attn_kernel,
                         cudaFuncAttributeMaxDynamicSharedMemorySize, ATT_SMEM);

    rope_tables_kernel<<<(SS * 64 + 255) / 256, 256>>>();

    dim3 ggrid(GN / 128, MM / 128);   // (16, 32) = 512 CTAs
    gemm_nt_bf16x3<<<ggrid, 256, G_SMEM>>>(x, Wq, q);
    gemm_nt_bf16x3<<<ggrid, 256, G_SMEM>>>(x, Wk, k);
    gemm_nt_bf16x3<<<ggrid, 256, G_SMEM>>>(x, Wv, v);

    int rt = MM * NH * 64;
    rope_apply_kernel<<<rt / 256, 256>>>(q);
    rope_apply_kernel<<<rt / 256, 256>>>(k);

    attn_kernel<<<dim3(SS / 64, NH, BB), 256, ATT_SMEM>>>();

    gemm_nt_bf16x3<<<ggrid, 256, G_SMEM>>>(ctx, Wo, out);
}